// round 15
// baseline (speedup 1.0000x reference)
#include <cuda_runtime.h>
#include <cuda_bf16.h>
#include <cstdint>

// ---------------- problem constants ----------------
#define IN_CH   512
#define HID     128
#define OUT_CH  128
#define MAXN    1000000
#define MAXSEG  50000
#define NT16    (IN_CH / 16)       // 32 k16-steps

// A-staging pipeline
#define NSTG      8
#define ROWB      80               // padded row stride (16B-aligned, conflict-light)
#define STG_BYTES (128 * ROWB)     // 10240
#define SMEM_A_BYTES (NSTG * STG_BYTES)        // 81920
#define SMEM_TOTAL   (SMEM_A_BYTES + 512)      // + s_a

// ---------------- device scratch ----------------
__device__ __align__(16) float g_h[(size_t)MAXN * HID];
__device__ float    g_a[MAXN];
__device__ float    g_e[MAXN];
__device__ unsigned g_smax[MAXSEG];
__device__ float    g_denom[MAXSEG];
__device__ __align__(16) float g_pooled[(size_t)MAXSEG * HID];
// W fragments in mma.sync B-operand register layout:
// index = ((t16 * 8) + n16blk) * 32 + lane, 16B each (regs b0,b1,b2,b3)
__device__ __align__(16) uint4 g_Wfh[NT16 * 8 * 32];
__device__ __align__(16) uint4 g_Wfl[NT16 * 8 * 32];

// ---------------- helpers ----------------
#define MMA16816(c, a0, a1, a2, a3, b0, b1) \
    asm volatile("mma.sync.aligned.m16n8k16.row.col.f32.bf16.bf16.f32 " \
                 "{%0,%1,%2,%3}, {%4,%5,%6,%7}, {%8,%9}, {%0,%1,%2,%3};" \
                 : "+f"((c)[0]), "+f"((c)[1]), "+f"((c)[2]), "+f"((c)[3]) \
                 : "r"(a0), "r"(a1), "r"(a2), "r"(a3), "r"(b0), "r"(b1))

__device__ __forceinline__ uint32_t smem_u32(const void* p) {
    uint32_t a;
    asm("{ .reg .u64 t; cvta.to.shared.u64 t, %1; cvt.u32.u64 %0, t; }"
        : "=r"(a) : "l"(p));
    return a;
}
__device__ __forceinline__ void cp16(uint32_t dst, const void* src, uint32_t srcsize) {
    asm volatile("cp.async.cg.shared.global [%0], [%1], 16, %2;"
                 :: "r"(dst), "l"(src), "r"(srcsize) : "memory");
}
__device__ __forceinline__ void cp_commit() {
    asm volatile("cp.async.commit_group;" ::: "memory");
}
__device__ __forceinline__ void cp_wait6() {
    asm volatile("cp.async.wait_group 6;" ::: "memory");
}

__device__ __forceinline__ uint32_t bf2bits(__nv_bfloat162 v) {
    return *reinterpret_cast<uint32_t*>(&v);
}
// split a float2 into bf16x2 hi and bf16x2 lo (lo = residual, rounded)
__device__ __forceinline__ void split2(float2 v, uint32_t& h, uint32_t& l) {
    __nv_bfloat162 hb = __floats2bfloat162_rn(v.x, v.y);
    float2 hf = __bfloat1622float2(hb);
    __nv_bfloat162 lb = __floats2bfloat162_rn(v.x - hf.x, v.y - hf.y);
    h = bf2bits(hb);
    l = bf2bits(lb);
}
__device__ __forceinline__ uint32_t pkbf(float a, float b) {
    return bf2bits(__floats2bfloat162_rn(a, b));
}

// f32x2 helpers (k_out)
__device__ __forceinline__ unsigned long long pk(float lo, float hi) {
    unsigned long long r;
    asm("mov.b64 %0, {%1, %2};" : "=l"(r) : "f"(lo), "f"(hi));
    return r;
}
__device__ __forceinline__ void unpk(unsigned long long v, float& lo, float& hi) {
    asm("mov.b64 {%0, %1}, %2;" : "=f"(lo), "=f"(hi) : "l"(v));
}
__device__ __forceinline__ void ffma2(unsigned long long& c, unsigned long long a,
                                      unsigned long long b) {
    asm("fma.rn.f32x2 %0, %1, %2, %0;" : "+l"(c) : "l"(a), "l"(b));
}
__device__ __forceinline__ unsigned mapf(float f) {
    unsigned b = __float_as_uint(f);
    return (b & 0x80000000u) ? ~b : (b | 0x80000000u);
}
__device__ __forceinline__ float unmapf(unsigned u) {
    return (u & 0x80000000u) ? __uint_as_float(u & 0x7FFFFFFFu)
                             : __uint_as_float(~u);
}

// ---------------- kernel: build W fragment tables ----------------
__global__ void k_prepw(const float* __restrict__ W1) {
    int t = blockIdx.x * blockDim.x + threadIdx.x;
    if (t >= NT16 * 8 * 32) return;
    int lane = t & 31;
    int p    = (t >> 5) & 7;       // n16 block
    int kt   = t >> 8;             // k16 step
    int tig = lane & 3, g = lane >> 2;
    int k0 = kt * 16 + tig * 2;
    int n0 = p * 16 + g;

    float wh[8], wl[8];
#pragma unroll
    for (int r = 0; r < 4; r++) {
        int k = k0 + (r & 1) * 8;
        int n = n0 + (r >> 1) * 8;
#pragma unroll
        for (int e = 0; e < 2; e++) {
            float w = W1[(size_t)(k + e) * HID + n];
            __nv_bfloat16 hb = __float2bfloat16(w);
            float hf = __bfloat162float(hb);
            wh[r * 2 + e] = hf;
            wl[r * 2 + e] = w - hf;
        }
    }
    size_t base = ((size_t)kt * 8 + p) * 32 + lane;
    uint4 H, L;
    H.x = pkbf(wh[0], wh[1]); H.y = pkbf(wh[2], wh[3]);
    H.z = pkbf(wh[4], wh[5]); H.w = pkbf(wh[6], wh[7]);
    L.x = pkbf(wl[0], wl[1]); L.y = pkbf(wl[2], wl[3]);
    L.z = pkbf(wl[4], wl[5]); L.w = pkbf(wl[6], wl[7]);
    g_Wfh[base] = H;
    g_Wfl[base] = L;
}

// ---------------- kernels: zero scratch (gemm1 stays in profiled slot #4) ----
__global__ void k_init_seg(int S) {
    int t = blockIdx.x * blockDim.x + threadIdx.x;
    int stride = gridDim.x * blockDim.x;
    for (int i = t; i < S; i += stride) { g_smax[i] = 0u; g_denom[i] = 0.0f; }
}
__global__ void k_init_pool(int S) {
    int t = blockIdx.x * blockDim.x + threadIdx.x;
    int stride = gridDim.x * blockDim.x;
    int tot4 = (S * HID) >> 2;
    float4* p4 = (float4*)g_pooled;
    float4 z = make_float4(0.f, 0.f, 0.f, 0.f);
    for (int i = t; i < tot4; i += stride) p4[i] = z;
}

// ---------------- GEMM1: 4(M)x2(N) warps, cp.async 8-stage A pipeline --------
// CTA = 256 threads = 8 warps; warp tile 32(M) x 64(N); CTA tile 128 rows.
__global__ void __launch_bounds__(256, 2)
k_gemm1(const float* __restrict__ x, const float* __restrict__ b1,
        const float* __restrict__ Wa, const float* __restrict__ ba, int N) {
    extern __shared__ __align__(16) char smem[];
    float* s_a = (float*)(smem + SMEM_A_BYTES);
    uint32_t sb = smem_u32(smem);
    int tid = threadIdx.x, wid = tid >> 5, lane = tid & 31;
    int mw = wid & 3, nw = wid >> 2;
    int tig = lane & 3, g = lane >> 2;
    long row0 = (long)blockIdx.x * 128;

    if (tid < 128) s_a[tid] = 0.0f;

    // ---- cp.async producer setup: thread -> (row = tid>>1, half = tid&1) ----
    int ldrow = tid >> 1;
    long gldrow = row0 + ldrow;
    bool ldok = gldrow < N;
    const char* xsrc = (const char*)(x + (ldok ? gldrow : 0) * (long)IN_CH)
                       + (tid & 1) * 32;
    uint32_t xdst = sb + (uint32_t)ldrow * ROWB + (tid & 1) * 32;
    uint32_t sz = ldok ? 16u : 0u;

    // prologue: issue stages 0..6 (one commit each)
#pragma unroll
    for (int s = 0; s < NSTG - 1; s++) {
        cp16(xdst + s * STG_BYTES, xsrc + (size_t)s * 64, sz);
        cp16(xdst + s * STG_BYTES + 16, xsrc + (size_t)s * 64 + 16, sz);
        cp_commit();
    }

    float acc[2][8][4];
#pragma unroll
    for (int a = 0; a < 2; a++)
#pragma unroll
        for (int b = 0; b < 8; b++)
#pragma unroll
            for (int q = 0; q < 4; q++) acc[a][b][q] = 0.0f;

    // B fragment pointers: advance by +256 uint4 (one t16 slice) per iter.
    const uint4* pBh = g_Wfh + (size_t)((nw * 4) * 32 + lane);
    const uint4* pBl = g_Wfl + (size_t)((nw * 4) * 32 + lane);

    // consumer fragment base offsets (within a stage)
    uint32_t fbase = (uint32_t)((mw * 32 + g) * ROWB + tig * 8);

#pragma unroll 1
    for (int t = 0; t < NT16; ++t) {
        cp_wait6();          // stage t complete (t+7 groups issued, <=6 pending)
        __syncthreads();

        // ---- LDS fragment elements + split to bf16 hi/lo ----
        uint32_t stg = (uint32_t)(t & (NSTG - 1)) * STG_BYTES;
        const char* sp = smem + stg + fbase;
        uint32_t ah[2][4], al[2][4];
#pragma unroll
        for (int mt = 0; mt < 2; mt++) {
            float2 v0 = *(const float2*)(sp + mt * (16 * ROWB));             // rr0 kh0
            float2 v1 = *(const float2*)(sp + mt * (16 * ROWB) + 8 * ROWB);  // rr1 kh0
            float2 v2 = *(const float2*)(sp + mt * (16 * ROWB) + 32);        // rr0 kh1
            float2 v3 = *(const float2*)(sp + mt * (16 * ROWB) + 8 * ROWB + 32);
            split2(v0, ah[mt][0], al[mt][0]);
            split2(v1, ah[mt][1], al[mt][1]);
            split2(v2, ah[mt][2], al[mt][2]);
            split2(v3, ah[mt][3], al[mt][3]);
        }

        // ---- B fragments via LDG (L2-hot table), JIT with 1-ahead ----
        uint4 bh = pBh[0], bl = pBl[0];
#pragma unroll
        for (int pp = 0; pp < 4; pp++) {
            uint4 nbh, nbl;
            if (pp < 3) { nbh = pBh[32 * (pp + 1)]; nbl = pBl[32 * (pp + 1)]; }
#pragma unroll
            for (int mt = 0; mt < 2; mt++) {
                MMA16816(acc[mt][2 * pp + 0], ah[mt][0], ah[mt][1], ah[mt][2], ah[mt][3], bh.x, bh.y);
                MMA16816(acc[mt][2 * pp + 1], ah[mt][0], ah[mt][1], ah[mt][2], ah[mt][3], bh.z, bh.w);
                MMA16816(acc[mt][2 * pp + 0], ah[mt][0], ah[mt][1], ah[mt][2], ah[mt][3], bl.x, bl.y);
                MMA16816(acc[mt][2 * pp + 1], ah[mt][0], ah[mt][1], ah[mt][2], ah[mt][3], bl.z, bl.w);
                MMA16816(acc[mt][2 * pp + 0], al[mt][0], al[mt][1], al[mt][2], al[mt][3], bh.x, bh.y);
                MMA16816(acc[mt][2 * pp + 1], al[mt][0], al[mt][1], al[mt][2], al[mt][3], bh.z, bh.w);
            }
            bh = nbh; bl = nbl;
        }
        pBh += 256; pBl += 256;

        // ---- issue stage t+7 (slot (t-1)&7: fully consumed one barrier ago)
        int s7 = t + NSTG - 1;
        if (s7 < NT16) {
            uint32_t dst = xdst + (uint32_t)(s7 & (NSTG - 1)) * STG_BYTES;
            cp16(dst, xsrc + (size_t)s7 * 64, sz);
            cp16(dst + 16, xsrc + (size_t)s7 * 64 + 16, sz);
        }
        cp_commit();   // commit every iter (possibly empty) to keep counts uniform
    }

    // ---- epilogue: bias + silu + logit + store h ----
    float2 b1v[8], wav[8];
#pragma unroll
    for (int nt = 0; nt < 8; nt++) {
        int cb = nw * 64 + nt * 8 + tig * 2;
        b1v[nt] = *(const float2*)&b1[cb];
        wav[nt] = *(const float2*)&Wa[cb];
    }
    long r0g = row0 + mw * 32 + g;
#pragma unroll
    for (int mt = 0; mt < 2; mt++) {
#pragma unroll
        for (int rh = 0; rh < 2; rh++) {
            long grow = r0g + mt * 16 + rh * 8;
            float part = 0.0f;
            if (grow < N) {
                float* hrow = g_h + (size_t)grow * HID;
#pragma unroll
                for (int nt = 0; nt < 8; nt++) {
                    float v0 = acc[mt][nt][rh * 2 + 0] + b1v[nt].x;
                    float v1 = acc[mt][nt][rh * 2 + 1] + b1v[nt].y;
                    float s0 = v0 / (1.0f + __expf(-v0));
                    float s1 = v1 / (1.0f + __expf(-v1));
                    part += s0 * wav[nt].x + s1 * wav[nt].y;
                    int cb = nw * 64 + nt * 8 + tig * 2;
                    *(float2*)(hrow + cb) = make_float2(s0, s1);
                }
            }
            part += __shfl_xor_sync(0xffffffffu, part, 1);
            part += __shfl_xor_sync(0xffffffffu, part, 2);
            if (tig == 0 && grow < N)
                atomicAdd(&s_a[(int)(grow - row0)], part);
        }
    }
    __syncthreads();
    if (tid < 128) {
        long row = row0 + tid;
        if (row < N) g_a[row] = s_a[tid] + ba[0];
    }
}

// ---------------- kernel: segment max ----------------
#define CHUNK 16
__global__ void k_segmax(const int* __restrict__ idx, int N) {
    int t = blockIdx.x * blockDim.x + threadIdx.x;
    int start = t * CHUNK;
    if (start >= N) return;
    int end = min(start + CHUNK, N);
    int cur = idx[start];
    float mx = g_a[start];
    for (int i = start + 1; i < end; i++) {
        int s = idx[i];
        float v = g_a[i];
        if (s == cur) mx = fmaxf(mx, v);
        else { atomicMax(&g_smax[cur], mapf(mx)); cur = s; mx = v; }
    }
    atomicMax(&g_smax[cur], mapf(mx));
}

// ---------------- kernel: exp + denom ----------------
__global__ void k_exp(const int* __restrict__ idx, int N) {
    int t = blockIdx.x * blockDim.x + threadIdx.x;
    int start = t * CHUNK;
    if (start >= N) return;
    int end = min(start + CHUNK, N);
    int cur = idx[start];
    float m = unmapf(g_smax[cur]);
    float ex = __expf(g_a[start] - m);
    g_e[start] = ex;
    float sum = ex;
    for (int i = start + 1; i < end; i++) {
        int s = idx[i];
        if (s != cur) {
            atomicAdd(&g_denom[cur], sum);
            cur = s; m = unmapf(g_smax[cur]); sum = 0.0f;
        }
        float e2 = __expf(g_a[i] - m);
        g_e[i] = e2;
        sum += e2;
    }
    atomicAdd(&g_denom[cur], sum);
}

// ---------------- kernel: weighted pooling over sorted runs ----------------
__global__ void __launch_bounds__(128)
k_pool(const int* __restrict__ idx, int N) {
    __shared__ int s_idx[256];
    __shared__ float s_w[256];
    int base = blockIdx.x * 256;
    int tid = threadIdx.x;
    for (int r = tid; r < 256; r += 128) {
        int row = base + r;
        if (row < N) {
            int sg = idx[row];
            s_idx[r] = sg;
            s_w[r] = g_e[row] / g_denom[sg];
        } else {
            s_idx[r] = -1;
        }
    }
    __syncthreads();

    int j = tid;
    float sum = 0.0f;
    int cur = s_idx[0];
#pragma unroll 1
    for (int rb = 0; rb < 256; rb += 8) {
        float hv[8];
#pragma unroll
        for (int u = 0; u < 8; u++)
            hv[u] = (s_idx[rb + u] >= 0)
                        ? g_h[(size_t)(base + rb + u) * HID + j] : 0.0f;
#pragma unroll
        for (int u = 0; u < 8; u++) {
            int sg = s_idx[rb + u];
            if (sg < 0) goto done;
            if (sg != cur) {
                atomicAdd(&g_pooled[(size_t)cur * HID + j], sum);
                sum = 0.0f; cur = sg;
            }
            sum += s_w[rb + u] * hv[u];
        }
    }
done:
    atomicAdd(&g_pooled[(size_t)cur * HID + j], sum);
}

// ---------------- kernel: out = pooled @ Wo + bo ----------------
__global__ void __launch_bounds__(256)
k_out(const float* __restrict__ Wo, const float* __restrict__ bo,
      float* __restrict__ out, int S) {
    __shared__ __align__(16) float Ps[64][HID];
    int tid = threadIdx.x;
    int row0 = blockIdx.x * 64;
#pragma unroll
    for (int i = 0; i < 8; i++) {
        int id = tid + i * 256;
        int r = id >> 5, c4 = id & 31;
        float4 v = make_float4(0.f, 0.f, 0.f, 0.f);
        if (row0 + r < S)
            v = *(const float4*)&g_pooled[(size_t)(row0 + r) * HID + c4 * 4];
        *(float4*)&Ps[r][c4 * 4] = v;
    }
    __syncthreads();

    int m_base = (tid >> 5) * 8;
    int n_base = (tid & 31) * 4;
    unsigned long long acc[8][2] = {};
#pragma unroll 4
    for (int k = 0; k < HID; k++) {
        float4 b = *(const float4*)&Wo[(size_t)k * OUT_CH + n_base];
        unsigned long long b0 = pk(b.x, b.y), b1p = pk(b.z, b.w);
#pragma unroll
        for (int mi = 0; mi < 8; mi++) {
            float av = Ps[m_base + mi][k];
            unsigned long long ad = pk(av, av);
            ffma2(acc[mi][0], ad, b0);
            ffma2(acc[mi][1], ad, b1p);
        }
    }
    float c0 = bo[n_base], c1 = bo[n_base + 1], c2 = bo[n_base + 2], c3 = bo[n_base + 3];
#pragma unroll
    for (int mi = 0; mi < 8; mi++) {
        int row = row0 + m_base + mi;
        if (row < S) {
            float l0, h0, l1, h1;
            unpk(acc[mi][0], l0, h0);
            unpk(acc[mi][1], l1, h1);
            *(float4*)&out[(size_t)row * OUT_CH + n_base] =
                make_float4(l0 + c0, h0 + c1, l1 + c2, h1 + c3);
        }
    }
}

// ---------------- launch ----------------
extern "C" void kernel_launch(void* const* d_in, const int* in_sizes, int n_in,
                              void* d_out, int out_size) {
    const float* x     = (const float*)d_in[0];
    const int*   index = (const int*)d_in[1];
    const float* W1 = (const float*)d_in[n_in - 6];
    const float* b1 = (const float*)d_in[n_in - 5];
    const float* Wa = (const float*)d_in[n_in - 4];
    const float* ba = (const float*)d_in[n_in - 3];
    const float* Wo = (const float*)d_in[n_in - 2];
    const float* bo = (const float*)d_in[n_in - 1];
    float* out = (float*)d_out;

    int N = in_sizes[0] / IN_CH;       // 1,000,000
    int S = out_size / OUT_CH;         // 50,000

    cudaFuncSetAttribute(k_gemm1, cudaFuncAttributeMaxDynamicSharedMemorySize,
                         SMEM_TOTAL);

    // launch order: gemm1 must be the 4th launch (ncu-profiled slot)
    k_prepw<<<(NT16 * 8 * 32 + 255) / 256, 256>>>(W1);                  // 1
    k_init_seg<<<64, 256>>>(S);                                         // 2
    k_init_pool<<<256, 256>>>(S);                                       // 3
    k_gemm1<<<(N + 127) / 128, 256, SMEM_TOTAL>>>(x, b1, Wa, ba, N);    // 4 <- profiled
    int ct = (N + CHUNK - 1) / CHUNK;
    k_segmax<<<(ct + 255) / 256, 256>>>(index, N);                      // 5
    k_exp<<<(ct + 255) / 256, 256>>>(index, N);                         // 6
    k_pool<<<(N + 255) / 256, 128>>>(index, N);                         // 7
    k_out<<<(S + 63) / 64, 256>>>(Wo, bo, out, S);                      // 8
}

// round 17
// speedup vs baseline: 1.3718x; 1.3718x over previous
#include <cuda_runtime.h>
#include <cuda_bf16.h>
#include <cstdint>

// ---------------- problem constants ----------------
#define IN_CH   512
#define HID     128
#define OUT_CH  128
#define MAXN    1000000
#define MAXSEG  50000
#define NT16    (IN_CH / 16)       // 32 k16-steps

// ---------------- device scratch ----------------
__device__ __align__(16) float g_h[(size_t)MAXN * HID];
__device__ float    g_a[MAXN];
__device__ float    g_e[MAXN];
__device__ unsigned g_smax[MAXSEG];
__device__ float    g_denom[MAXSEG];
__device__ __align__(16) float g_pooled[(size_t)MAXSEG * HID];
// W fragments in mma.sync B-operand register layout:
// index = ((t16 * 8) + n16blk) * 32 + lane, 16B each (regs b0,b1,b2,b3)
__device__ __align__(16) uint4 g_Wfh[NT16 * 8 * 32];
__device__ __align__(16) uint4 g_Wfl[NT16 * 8 * 32];

// ---------------- helpers ----------------
#define MMA16816(c, a0, a1, a2, a3, b0, b1) \
    asm volatile("mma.sync.aligned.m16n8k16.row.col.f32.bf16.bf16.f32 " \
                 "{%0,%1,%2,%3}, {%4,%5,%6,%7}, {%8,%9}, {%0,%1,%2,%3};" \
                 : "+f"((c)[0]), "+f"((c)[1]), "+f"((c)[2]), "+f"((c)[3]) \
                 : "r"(a0), "r"(a1), "r"(a2), "r"(a3), "r"(b0), "r"(b1))

__device__ __forceinline__ uint32_t bf2bits(__nv_bfloat162 v) {
    return *reinterpret_cast<uint32_t*>(&v);
}
// split a float2 into bf16x2 hi and bf16x2 lo (lo = residual, rounded)
__device__ __forceinline__ void split2(float2 v, uint32_t& h, uint32_t& l) {
    __nv_bfloat162 hb = __floats2bfloat162_rn(v.x, v.y);
    float2 hf = __bfloat1622float2(hb);
    __nv_bfloat162 lb = __floats2bfloat162_rn(v.x - hf.x, v.y - hf.y);
    h = bf2bits(hb);
    l = bf2bits(lb);
}
__device__ __forceinline__ uint32_t pkbf(float a, float b) {
    return bf2bits(__floats2bfloat162_rn(a, b));
}

// f32x2 helpers (k_out)
__device__ __forceinline__ unsigned long long pk(float lo, float hi) {
    unsigned long long r;
    asm("mov.b64 %0, {%1, %2};" : "=l"(r) : "f"(lo), "f"(hi));
    return r;
}
__device__ __forceinline__ void unpk(unsigned long long v, float& lo, float& hi) {
    asm("mov.b64 {%0, %1}, %2;" : "=f"(lo), "=f"(hi) : "l"(v));
}
__device__ __forceinline__ void ffma2(unsigned long long& c, unsigned long long a,
                                      unsigned long long b) {
    asm("fma.rn.f32x2 %0, %1, %2, %0;" : "+l"(c) : "l"(a), "l"(b));
}
__device__ __forceinline__ unsigned mapf(float f) {
    unsigned b = __float_as_uint(f);
    return (b & 0x80000000u) ? ~b : (b | 0x80000000u);
}
__device__ __forceinline__ float unmapf(unsigned u) {
    return (u & 0x80000000u) ? __uint_as_float(u & 0x7FFFFFFFu)
                             : __uint_as_float(~u);
}

// ---------------- kernel: build W fragment tables ----------------
__global__ void k_prepw(const float* __restrict__ W1) {
    int t = blockIdx.x * blockDim.x + threadIdx.x;
    if (t >= NT16 * 8 * 32) return;
    int lane = t & 31;
    int p    = (t >> 5) & 7;       // n16 block
    int kt   = t >> 8;             // k16 step
    int tig = lane & 3, g = lane >> 2;
    int k0 = kt * 16 + tig * 2;
    int n0 = p * 16 + g;

    float wh[8], wl[8];
#pragma unroll
    for (int r = 0; r < 4; r++) {
        int k = k0 + (r & 1) * 8;
        int n = n0 + (r >> 1) * 8;
#pragma unroll
        for (int e = 0; e < 2; e++) {
            float w = W1[(size_t)(k + e) * HID + n];
            __nv_bfloat16 hb = __float2bfloat16(w);
            float hf = __bfloat162float(hb);
            wh[r * 2 + e] = hf;
            wl[r * 2 + e] = w - hf;
        }
    }
    size_t base = ((size_t)kt * 8 + p) * 32 + lane;
    uint4 H, L;
    H.x = pkbf(wh[0], wh[1]); H.y = pkbf(wh[2], wh[3]);
    H.z = pkbf(wh[4], wh[5]); H.w = pkbf(wh[6], wh[7]);
    L.x = pkbf(wl[0], wl[1]); L.y = pkbf(wl[2], wl[3]);
    L.z = pkbf(wl[4], wl[5]); L.w = pkbf(wl[6], wl[7]);
    g_Wfh[base] = H;
    g_Wfl[base] = L;
}

// ---------------- kernels: zero scratch (gemm1 stays in profiled slot #4) ----
__global__ void k_init_seg(int S) {
    int t = blockIdx.x * blockDim.x + threadIdx.x;
    int stride = gridDim.x * blockDim.x;
    for (int i = t; i < S; i += stride) { g_smax[i] = 0u; g_denom[i] = 0.0f; }
}
__global__ void k_init_pool(int S) {
    int t = blockIdx.x * blockDim.x + threadIdx.x;
    int stride = gridDim.x * blockDim.x;
    int tot4 = (S * HID) >> 2;
    float4* p4 = (float4*)g_pooled;
    float4 z = make_float4(0.f, 0.f, 0.f, 0.f);
    for (int i = t; i < tot4; i += stride) p4[i] = z;
}

// ---------------- GEMM1: 4(M)x2(N) warps, 16x64 warp tile, occupancy 3 ------
// CTA = 256 threads = 8 warps; CTA tile 64 rows x 128 cols; grid = N/64.
__global__ void __launch_bounds__(256, 3)
k_gemm1(const float* __restrict__ x, const float* __restrict__ b1,
        const float* __restrict__ Wa, const float* __restrict__ ba, int N) {
    __shared__ float s_a[64];
    int tid = threadIdx.x, wid = tid >> 5, lane = tid & 31;
    int mw = wid & 3, nw = wid >> 2;
    int tig = lane & 3, g = lane >> 2;
    long row0 = (long)blockIdx.x * 64;

    if (tid < 64) s_a[tid] = 0.0f;
    __syncthreads();

    // per-lane A row pointers: rows row0 + mw*16 + rr*8 + g
    long rA = row0 + mw * 16 + g;
    long rB = rA + 8;
    bool ok0 = rA < N, ok1 = rB < N;
    const float* xp0 = x + (ok0 ? rA : 0) * (long)IN_CH;
    const float* xp1 = x + (ok1 ? rB : 0) * (long)IN_CH;

    float acc[8][4];
#pragma unroll
    for (int b = 0; b < 8; b++)
#pragma unroll
        for (int q = 0; q < 4; q++) acc[b][q] = 0.0f;

    // B fragment pointers: advance by +256 uint4 (one t16 slice) per iter.
    const uint4* pBh = g_Wfh + (size_t)((nw * 4) * 32 + lane);
    const uint4* pBl = g_Wfl + (size_t)((nw * 4) * 32 + lane);
    const float2 z2 = make_float2(0.f, 0.f);

#pragma unroll 1
    for (int t = 0; t < NT16; ++t) {
        int c0 = t * 16 + tig * 2;
        // ---- A loads (fp32, exactly the fragment elements) ----
        float2 v0 = ok0 ? *(const float2*)(xp0 + c0) : z2;
        float2 v1 = ok1 ? *(const float2*)(xp1 + c0) : z2;
        float2 v2 = ok0 ? *(const float2*)(xp0 + c0 + 8) : z2;
        float2 v3 = ok1 ? *(const float2*)(xp1 + c0 + 8) : z2;
        // L2 prefetch next-next k16 line of x
        if (tig == 0 && t + 2 < NT16) {
            if (ok0) asm volatile("prefetch.global.L2 [%0];" :: "l"(xp0 + (t + 2) * 16));
            if (ok1) asm volatile("prefetch.global.L2 [%0];" :: "l"(xp1 + (t + 2) * 16));
        }
        // ---- split to bf16 hi/lo fragments in registers ----
        uint32_t ah[4], al[4];
        split2(v0, ah[0], al[0]);
        split2(v1, ah[1], al[1]);
        split2(v2, ah[2], al[2]);
        split2(v3, ah[3], al[3]);

        // ---- 4 n16 blocks; B fragments JIT (occupancy hides latency) ----
#pragma unroll
        for (int pp = 0; pp < 4; pp++) {
            uint4 bh = pBh[32 * pp];
            uint4 bl = pBl[32 * pp];
            MMA16816(acc[2 * pp + 0], ah[0], ah[1], ah[2], ah[3], bh.x, bh.y);
            MMA16816(acc[2 * pp + 1], ah[0], ah[1], ah[2], ah[3], bh.z, bh.w);
            MMA16816(acc[2 * pp + 0], ah[0], ah[1], ah[2], ah[3], bl.x, bl.y);
            MMA16816(acc[2 * pp + 1], ah[0], ah[1], ah[2], ah[3], bl.z, bl.w);
            MMA16816(acc[2 * pp + 0], al[0], al[1], al[2], al[3], bh.x, bh.y);
            MMA16816(acc[2 * pp + 1], al[0], al[1], al[2], al[3], bh.z, bh.w);
        }
        pBh += 256; pBl += 256;
    }

    // ---- epilogue: bias + silu + logit + store h ----
#pragma unroll
    for (int rh = 0; rh < 2; rh++) {
        long grow = rh ? rB : rA;
        bool okr = rh ? ok1 : ok0;
        float part = 0.0f;
        if (okr) {
            float* hrow = g_h + (size_t)grow * HID;
#pragma unroll
            for (int nt = 0; nt < 8; nt++) {
                int cb = nw * 64 + nt * 8 + tig * 2;
                float2 bb = *(const float2*)&b1[cb];
                float2 ww = *(const float2*)&Wa[cb];
                float u0 = acc[nt][rh * 2 + 0] + bb.x;
                float u1 = acc[nt][rh * 2 + 1] + bb.y;
                float s0 = u0 / (1.0f + __expf(-u0));
                float s1 = u1 / (1.0f + __expf(-u1));
                part += s0 * ww.x + s1 * ww.y;
                *(float2*)(hrow + cb) = make_float2(s0, s1);
            }
        }
        part += __shfl_xor_sync(0xffffffffu, part, 1);
        part += __shfl_xor_sync(0xffffffffu, part, 2);
        if (tig == 0 && okr)
            atomicAdd(&s_a[(int)(grow - row0)], part);
    }
    __syncthreads();
    if (tid < 64) {
        long row = row0 + tid;
        if (row < N) g_a[row] = s_a[tid] + ba[0];
    }
}

// ---------------- kernel: segment max ----------------
#define CHUNK 16
__global__ void k_segmax(const int* __restrict__ idx, int N) {
    int t = blockIdx.x * blockDim.x + threadIdx.x;
    int start = t * CHUNK;
    if (start >= N) return;
    int end = min(start + CHUNK, N);
    int cur = idx[start];
    float mx = g_a[start];
    for (int i = start + 1; i < end; i++) {
        int s = idx[i];
        float v = g_a[i];
        if (s == cur) mx = fmaxf(mx, v);
        else { atomicMax(&g_smax[cur], mapf(mx)); cur = s; mx = v; }
    }
    atomicMax(&g_smax[cur], mapf(mx));
}

// ---------------- kernel: exp + denom ----------------
__global__ void k_exp(const int* __restrict__ idx, int N) {
    int t = blockIdx.x * blockDim.x + threadIdx.x;
    int start = t * CHUNK;
    if (start >= N) return;
    int end = min(start + CHUNK, N);
    int cur = idx[start];
    float m = unmapf(g_smax[cur]);
    float ex = __expf(g_a[start] - m);
    g_e[start] = ex;
    float sum = ex;
    for (int i = start + 1; i < end; i++) {
        int s = idx[i];
        if (s != cur) {
            atomicAdd(&g_denom[cur], sum);
            cur = s; m = unmapf(g_smax[cur]); sum = 0.0f;
        }
        float e2 = __expf(g_a[i] - m);
        g_e[i] = e2;
        sum += e2;
    }
    atomicAdd(&g_denom[cur], sum);
}

// ---------------- kernel: weighted pooling over sorted runs ----------------
__global__ void __launch_bounds__(128)
k_pool(const int* __restrict__ idx, int N) {
    __shared__ int s_idx[256];
    __shared__ float s_w[256];
    int base = blockIdx.x * 256;
    int tid = threadIdx.x;
    for (int r = tid; r < 256; r += 128) {
        int row = base + r;
        if (row < N) {
            int sg = idx[row];
            s_idx[r] = sg;
            s_w[r] = g_e[row] / g_denom[sg];
        } else {
            s_idx[r] = -1;
        }
    }
    __syncthreads();

    int j = tid;
    float sum = 0.0f;
    int cur = s_idx[0];
#pragma unroll 1
    for (int rb = 0; rb < 256; rb += 8) {
        float hv[8];
#pragma unroll
        for (int u = 0; u < 8; u++)
            hv[u] = (s_idx[rb + u] >= 0)
                        ? g_h[(size_t)(base + rb + u) * HID + j] : 0.0f;
#pragma unroll
        for (int u = 0; u < 8; u++) {
            int sg = s_idx[rb + u];
            if (sg < 0) goto done;
            if (sg != cur) {
                atomicAdd(&g_pooled[(size_t)cur * HID + j], sum);
                sum = 0.0f; cur = sg;
            }
            sum += s_w[rb + u] * hv[u];
        }
    }
done:
    atomicAdd(&g_pooled[(size_t)cur * HID + j], sum);
}

// ---------------- kernel: out = pooled @ Wo + bo ----------------
__global__ void __launch_bounds__(256)
k_out(const float* __restrict__ Wo, const float* __restrict__ bo,
      float* __restrict__ out, int S) {
    __shared__ __align__(16) float Ps[64][HID];
    int tid = threadIdx.x;
    int row0 = blockIdx.x * 64;
#pragma unroll
    for (int i = 0; i < 8; i++) {
        int id = tid + i * 256;
        int r = id >> 5, c4 = id & 31;
        float4 v = make_float4(0.f, 0.f, 0.f, 0.f);
        if (row0 + r < S)
            v = *(const float4*)&g_pooled[(size_t)(row0 + r) * HID + c4 * 4];
        *(float4*)&Ps[r][c4 * 4] = v;
    }
    __syncthreads();

    int m_base = (tid >> 5) * 8;
    int n_base = (tid & 31) * 4;
    unsigned long long acc[8][2] = {};
#pragma unroll 4
    for (int k = 0; k < HID; k++) {
        float4 b = *(const float4*)&Wo[(size_t)k * OUT_CH + n_base];
        unsigned long long b0 = pk(b.x, b.y), b1p = pk(b.z, b.w);
#pragma unroll
        for (int mi = 0; mi < 8; mi++) {
            float av = Ps[m_base + mi][k];
            unsigned long long ad = pk(av, av);
            ffma2(acc[mi][0], ad, b0);
            ffma2(acc[mi][1], ad, b1p);
        }
    }
    float c0 = bo[n_base], c1 = bo[n_base + 1], c2 = bo[n_base + 2], c3 = bo[n_base + 3];
#pragma unroll
    for (int mi = 0; mi < 8; mi++) {
        int row = row0 + m_base + mi;
        if (row < S) {
            float l0, h0, l1, h1;
            unpk(acc[mi][0], l0, h0);
            unpk(acc[mi][1], l1, h1);
            *(float4*)&out[(size_t)row * OUT_CH + n_base] =
                make_float4(l0 + c0, h0 + c1, l1 + c2, h1 + c3);
        }
    }
}

// ---------------- launch ----------------
extern "C" void kernel_launch(void* const* d_in, const int* in_sizes, int n_in,
                              void* d_out, int out_size) {
    const float* x     = (const float*)d_in[0];
    const int*   index = (const int*)d_in[1];
    const float* W1 = (const float*)d_in[n_in - 6];
    const float* b1 = (const float*)d_in[n_in - 5];
    const float* Wa = (const float*)d_in[n_in - 4];
    const float* ba = (const float*)d_in[n_in - 3];
    const float* Wo = (const float*)d_in[n_in - 2];
    const float* bo = (const float*)d_in[n_in - 1];
    float* out = (float*)d_out;

    int N = in_sizes[0] / IN_CH;       // 1,000,000
    int S = out_size / OUT_CH;         // 50,000

    // launch order: gemm1 must be the 4th launch (ncu-profiled slot)
    k_prepw<<<(NT16 * 8 * 32 + 255) / 256, 256>>>(W1);       // 1
    k_init_seg<<<64, 256>>>(S);                              // 2
    k_init_pool<<<256, 256>>>(S);                            // 3
    k_gemm1<<<(N + 63) / 64, 256>>>(x, b1, Wa, ba, N);       // 4  <- profiled
    int ct = (N + CHUNK - 1) / CHUNK;
    k_segmax<<<(ct + 255) / 256, 256>>>(index, N);           // 5
    k_exp<<<(ct + 255) / 256, 256>>>(index, N);              // 6
    k_pool<<<(N + 255) / 256, 128>>>(index, N);              // 7
    k_out<<<(S + 63) / 64, 256>>>(Wo, bo, out, S);           // 8
}